// round 16
// baseline (speedup 1.0000x reference)
#include <cuda_runtime.h>
#include <cstdint>
#include <cstddef>

#define TN 32768
#define NB 64
#define SEQ 512
#define HD 128
#define G4 512
#define NE 1048576
#define FCN 262144

// ---------------- scratch (device globals; allocation-free) ----------------
__device__ float g_deg[TN];          // deg -> dinv (in place)
__device__ float g_xw[TN * HD];      // x @ W_gcn (pre-norm)
__device__ float g_h[TN * HD];       // GCN output / LSTM-1 input
__device__ float g_gates[TN * G4];   // 64 MB x-part gate buffer (reused per layer)
__device__ float g_seq1[TN * HD];    // LSTM layer-1 output sequence
__device__ float g_last2[NB * HD];   // LSTM layer-2 LAST hidden (FC input)
// dst-CSR for the edge scatter (int only; no float atomics anywhere)
__device__ int g_cnt[TN];
__device__ int g_cur[TN];
__device__ int g_off[TN + 1];
__device__ int g_eid[NE];

#define FMA2(a, b, c) asm("fma.rn.f32x2 %0,%1,%2,%0;" : "+l"(a) : "l"(b), "l"(c))
union U2 { unsigned long long u; float2 f; };

__device__ __forceinline__ float fsig(float x) {        // sigmoid, MUFU-based
    return __fdividef(1.0f, 1.0f + __expf(-x));
}
__device__ __forceinline__ float ftanh(float x) {       // tanh via exp, ~1e-6 err
    return 1.0f - __fdividef(2.0f, __expf(2.0f * x) + 1.0f);
}
__device__ __forceinline__ uint32_t smem_u32(const void* p) {
    uint32_t a;
    asm("{ .reg .u64 t; cvta.to.shared.u64 t, %1; cvt.u32.u64 %0, t; }" : "=r"(a) : "l"(p));
    return a;
}

// ---------------- degree / norm / CSR count ----------------
__global__ void k_deg_init() {
    int i = blockIdx.x * 256 + threadIdx.x;
    g_deg[i] = 1.0f;                                 // self-loop weight
    g_cnt[i] = 0;
    g_cur[i] = 0;
}
// edge_index is int32 on the device (harness downcasts int64 inputs).
__global__ void k_deg_acc(const int* __restrict__ ei, const float* __restrict__ ew) {
    int e = blockIdx.x * 256 + threadIdx.x;
    int d = ei[NE + e];
    atomicAdd(&g_deg[d], ew[e]);
    atomicAdd(&g_cnt[d], 1);
}
__global__ void k_dinv() {
    int i = blockIdx.x * 256 + threadIdx.x;
    g_deg[i] = rsqrtf(g_deg[i]);                     // deg >= 1 always
}

// ---------------- exclusive scan of g_cnt -> g_off (1 block, 1024 thr) -----
__global__ void __launch_bounds__(1024) k_scan() {
    __shared__ int ssum[1024];
    int t = threadIdx.x;
    int base = t * 32;
    int loc[32];
    int s = 0;
    const int4* cp = (const int4*)(g_cnt + base);
#pragma unroll
    for (int i = 0; i < 8; i++) {
        int4 q = cp[i];
        loc[4 * i + 0] = s; s += q.x;
        loc[4 * i + 1] = s; s += q.y;
        loc[4 * i + 2] = s; s += q.z;
        loc[4 * i + 3] = s; s += q.w;
    }
    ssum[t] = s;
    __syncthreads();
    for (int d = 1; d < 1024; d <<= 1) {
        int v = (t >= d) ? ssum[t - d] : 0;
        __syncthreads();
        ssum[t] += v;
        __syncthreads();
    }
    int excl = (t == 0) ? 0 : ssum[t - 1];
    int4* op = (int4*)(g_off + base);
#pragma unroll
    for (int i = 0; i < 8; i++) {
        int4 q;
        q.x = excl + loc[4 * i + 0];
        q.y = excl + loc[4 * i + 1];
        q.z = excl + loc[4 * i + 2];
        q.w = excl + loc[4 * i + 3];
        op[i] = q;
    }
    if (t == 1023) g_off[TN] = ssum[1023];
}

__global__ void k_fill(const int* __restrict__ ei) {
    int e = blockIdx.x * 256 + threadIdx.x;
    int d = ei[NE + e];
    int pos = g_off[d] + atomicAdd(&g_cur[d], 1);
    g_eid[pos] = e;
}

// ---------------- xw = x @ W_gcn ; g_h = b_gcn + dinv^2 * xw ----------------
__global__ void __launch_bounds__(256) k_xw(const float* __restrict__ X,
                                            const float* __restrict__ W,
                                            const float* __restrict__ bg) {
    __shared__ float As[16][128];
    __shared__ float Bs[16][128];
    int m0 = blockIdx.x * 128;
    int tid = threadIdx.x;
    int tc = tid & 15, tr = tid >> 4;
    int lr = tid >> 1, lc = (tid & 1) * 8;           // A loader
    int bk = tid >> 4, bn = (tid & 15) * 8;          // B loader
    float acc[8][8] = {};
    for (int k0 = 0; k0 < 128; k0 += 16) {
        float4 a0 = *(const float4*)(X + (size_t)(m0 + lr) * 128 + k0 + lc);
        float4 a1 = *(const float4*)(X + (size_t)(m0 + lr) * 128 + k0 + lc + 4);
        float4 b0 = *(const float4*)(W + (size_t)(k0 + bk) * 128 + bn);
        float4 b1 = *(const float4*)(W + (size_t)(k0 + bk) * 128 + bn + 4);
        __syncthreads();
        As[lc + 0][lr] = a0.x; As[lc + 1][lr] = a0.y; As[lc + 2][lr] = a0.z; As[lc + 3][lr] = a0.w;
        As[lc + 4][lr] = a1.x; As[lc + 5][lr] = a1.y; As[lc + 6][lr] = a1.z; As[lc + 7][lr] = a1.w;
        *(float4*)&Bs[bk][bn] = b0;
        *(float4*)&Bs[bk][bn + 4] = b1;
        __syncthreads();
#pragma unroll
        for (int k = 0; k < 16; k++) {
            float av[8], bv[8];
            *(float4*)&av[0] = *(const float4*)&As[k][tr * 8];
            *(float4*)&av[4] = *(const float4*)&As[k][tr * 8 + 4];
            *(float4*)&bv[0] = *(const float4*)&Bs[k][tc * 8];
            *(float4*)&bv[4] = *(const float4*)&Bs[k][tc * 8 + 4];
#pragma unroll
            for (int i = 0; i < 8; i++)
#pragma unroll
                for (int jj = 0; jj < 8; jj++)
                    acc[i][jj] = fmaf(av[i], bv[jj], acc[i][jj]);
        }
    }
#pragma unroll
    for (int i = 0; i < 8; i++) {
        int m = m0 + tr * 8 + i;
        float di = g_deg[m];
        float di2 = di * di;
#pragma unroll
        for (int jj = 0; jj < 8; jj++) {
            int n = tc * 8 + jj;
            float v = acc[i][jj];
            g_xw[(size_t)m * 128 + n] = v;
            g_h[(size_t)m * 128 + n] = bg[n] + v * di2;
        }
    }
}

// ---------------- gather: g_h[d] += sum_e norm_e * g_xw[src_e] -------------
__global__ void __launch_bounds__(256) k_gather(const int* __restrict__ ei,
                                                const float* __restrict__ ew) {
    int d = blockIdx.x * 8 + (threadIdx.x >> 5);
    int lane = threadIdx.x & 31;
    int beg = g_off[d], end = g_off[d + 1];
    float dd = g_deg[d];
    float4 acc = {0.f, 0.f, 0.f, 0.f};
    int p = beg;
    for (; p + 2 <= end; p += 2) {
        int e0 = g_eid[p], e1 = g_eid[p + 1];
        int s0 = ei[e0], s1 = ei[e1];
        float n0 = g_deg[s0] * ew[e0] * dd;
        float n1 = g_deg[s1] * ew[e1] * dd;
        float4 v0 = ((const float4*)(g_xw + (size_t)s0 * HD))[lane];
        float4 v1 = ((const float4*)(g_xw + (size_t)s1 * HD))[lane];
        acc.x = fmaf(n0, v0.x, fmaf(n1, v1.x, acc.x));
        acc.y = fmaf(n0, v0.y, fmaf(n1, v1.y, acc.y));
        acc.z = fmaf(n0, v0.z, fmaf(n1, v1.z, acc.z));
        acc.w = fmaf(n0, v0.w, fmaf(n1, v1.w, acc.w));
    }
    if (p < end) {
        int e0 = g_eid[p];
        int s0 = ei[e0];
        float n0 = g_deg[s0] * ew[e0] * dd;
        float4 v0 = ((const float4*)(g_xw + (size_t)s0 * HD))[lane];
        acc.x = fmaf(n0, v0.x, acc.x); acc.y = fmaf(n0, v0.y, acc.y);
        acc.z = fmaf(n0, v0.z, acc.z); acc.w = fmaf(n0, v0.w, acc.w);
    }
    float4* dst = (float4*)(g_h + (size_t)d * HD) + lane;
    float4 cur = *dst;                               // bias + self-loop term
    cur.x += acc.x; cur.y += acc.y; cur.z += acc.z; cur.w += acc.w;
    *dst = cur;
}

// ---------------- gate GEMM: g_gates = A @ wih^T + bih + bhh (f32x2) -------
__global__ void __launch_bounds__(256) k_gates(const float* __restrict__ Bw,
                                               const float* __restrict__ c1,
                                               const float* __restrict__ c2, int src) {
    const float* A = src ? g_seq1 : g_h;
    __shared__ float As[16][128];
    __shared__ float Bs[16][128];
    int m0 = blockIdx.y * 128, n0 = blockIdx.x * 128;
    int tid = threadIdx.x;
    int tc = tid & 15, tr = tid >> 4;
    int lr = tid >> 1, lc = (tid & 1) * 8;
    unsigned long long acc[8][4] = {};
    for (int k0 = 0; k0 < 128; k0 += 16) {
        float4 a0 = *(const float4*)(A + (size_t)(m0 + lr) * 128 + k0 + lc);
        float4 a1 = *(const float4*)(A + (size_t)(m0 + lr) * 128 + k0 + lc + 4);
        float4 p0 = *(const float4*)(Bw + (size_t)(n0 + lr) * 128 + k0 + lc);
        float4 p1 = *(const float4*)(Bw + (size_t)(n0 + lr) * 128 + k0 + lc + 4);
        __syncthreads();
        As[lc + 0][lr] = a0.x; As[lc + 1][lr] = a0.y; As[lc + 2][lr] = a0.z; As[lc + 3][lr] = a0.w;
        As[lc + 4][lr] = a1.x; As[lc + 5][lr] = a1.y; As[lc + 6][lr] = a1.z; As[lc + 7][lr] = a1.w;
        Bs[lc + 0][lr] = p0.x; Bs[lc + 1][lr] = p0.y; Bs[lc + 2][lr] = p0.z; Bs[lc + 3][lr] = p0.w;
        Bs[lc + 4][lr] = p1.x; Bs[lc + 5][lr] = p1.y; Bs[lc + 6][lr] = p1.z; Bs[lc + 7][lr] = p1.w;
        __syncthreads();
#pragma unroll
        for (int k = 0; k < 16; k++) {
            float av[8];
            *(float4*)&av[0] = *(const float4*)&As[k][tr * 8];
            *(float4*)&av[4] = *(const float4*)&As[k][tr * 8 + 4];
            ulonglong2 q0 = *(const ulonglong2*)&Bs[k][tc * 8];
            ulonglong2 q1 = *(const ulonglong2*)&Bs[k][tc * 8 + 4];
            unsigned long long bv[4] = {q0.x, q0.y, q1.x, q1.y};
#pragma unroll
            for (int i = 0; i < 8; i++) {
                U2 ap; ap.f.x = av[i]; ap.f.y = av[i];
#pragma unroll
                for (int jj = 0; jj < 4; jj++) FMA2(acc[i][jj], ap.u, bv[jj]);
            }
        }
    }
    float bias[8];
#pragma unroll
    for (int jj = 0; jj < 8; jj++) {
        int n = n0 + tc * 8 + jj;
        bias[jj] = c1[n] + c2[n];
    }
#pragma unroll
    for (int i = 0; i < 8; i++) {
        int m = m0 + tr * 8 + i;
        float o[8];
#pragma unroll
        for (int jj = 0; jj < 4; jj++) {
            U2 v; v.u = acc[i][jj];
            o[2 * jj] = v.f.x + bias[2 * jj];
            o[2 * jj + 1] = v.f.y + bias[2 * jj + 1];
        }
        *(float4*)(g_gates + (size_t)m * 512 + n0 + tc * 8) = *(float4*)&o[0];
        *(float4*)(g_gates + (size_t)m * 512 + n0 + tc * 8 + 4) = *(float4*)&o[4];
    }
}

// ---------------- LSTM recurrence: 2-CTA cluster per batch -----------------
// Gate remap: CTA r owns cols {t*128 + r*64 + hl} => act local for h-idx
// [r*64, r*64+64). Sync = SPLIT cluster barrier: arrive right after act
// (release covers the 64-float h push to peer), next step dots the LOCAL h
// half first, then waits, then dots the peer half. Barrier latency is
// overlapped by gx prefetch + local-half dot. sH parity double-buffered:
// buffer s&1 written by act(s)/peer push(s), read only by dots s-1 and s+1;
// every conflicting pair is ordered through the arrive(s)/wait(s) chain.
__global__ void __launch_bounds__(256, 1) __cluster_dims__(2, 1, 1)
k_rec(const float* __restrict__ whh, int layer) {
    __shared__ float sH[2][HD];
    __shared__ float sGl[256];
    int j = threadIdx.x;
    unsigned rank;
    asm("mov.u32 %0, %%cluster_ctarank;" : "=r"(rank));
    int b = blockIdx.x >> 1;                         // batch id
    int t = j >> 6;                                  // gate type 0..3 (i,f,g,o)
    int hl = j & 63;                                 // local h index
    int hid = rank * 64 + hl;                        // global h index
    int gcol = t * 128 + hid;                        // owned gate column
    const unsigned long long* wrow = (const unsigned long long*)(whh + (size_t)gcol * HD);
    unsigned long long wr[64];
#pragma unroll
    for (int p = 0; p < 64; p++) wr[p] = wrow[p];    // full whh row in registers
    uint32_t sh_local = smem_u32(&sH[0][0]);
    uint32_t sh_peer;
    asm("mapa.shared::cluster.u32 %0, %1, %2;" : "=r"(sh_peer) : "r"(sh_local), "r"(rank ^ 1u));
    if (j < HD) sH[1][j] = 0.0f;                     // step-0 dot reads buf 1
    float c = 0.0f;
    __syncthreads();
    asm volatile("barrier.cluster.arrive.aligned;" ::: "memory");
    asm volatile("barrier.cluster.wait.aligned;" ::: "memory");

    const float* gxb = g_gates + (size_t)b * SEQ * G4 + gcol;
    float* hob = g_seq1 + (size_t)b * SEQ * HD;
    const int qb = rank * 16;                        // local-half ulonglong2 base
    const int qp = (rank ^ 1) * 16;                  // peer-half base
    float gxv = gxb[0];
    for (int s = 0; s < SEQ; s++) {
        const ulonglong2* h2 = (const ulonglong2*)sH[(s + 1) & 1];
        unsigned long long a0 = 0ULL, a1 = 0ULL;
#pragma unroll
        for (int q = 0; q < 16; q++) {               // LOCAL half: no peer dep
            ulonglong2 hh = h2[qb + q];
            FMA2(a0, wr[2 * (qb + q)], hh.x);
            FMA2(a1, wr[2 * (qb + q) + 1], hh.y);
        }
        float gxn = (s < SEQ - 1) ? gxb[(size_t)(s + 1) * G4] : 0.0f;
        if (s > 0)                                   // peer h of step s-1 ready
            asm volatile("barrier.cluster.wait.aligned;" ::: "memory");
#pragma unroll
        for (int q = 0; q < 16; q++) {               // PEER half
            ulonglong2 hh = h2[qp + q];
            FMA2(a0, wr[2 * (qp + q)], hh.x);
            FMA2(a1, wr[2 * (qp + q) + 1], hh.y);
        }
        U2 u0, u1; u0.u = a0; u1.u = a1;
        sGl[j] = gxv + (u0.f.x + u0.f.y) + (u1.f.x + u1.f.y);
        __syncthreads();
        if (j < 64) {                                // all 4 gates local
            float gi = sGl[j], gf = sGl[64 + j], gg = sGl[128 + j], go = sGl[192 + j];
            c = fsig(gf) * c + fsig(gi) * ftanh(gg);
            float h = fsig(go) * ftanh(c);
            int wb = s & 1;
            sH[wb][hid] = h;
            if (s < SEQ - 1) {
                uint32_t off = (uint32_t)(wb * HD + hid) * 4u;
                asm volatile("st.shared::cluster.f32 [%0], %1;"
                             :: "r"(sh_peer + off), "f"(h) : "memory");
            }
            if (layer == 0) hob[(size_t)s * HD + hid] = h;
            else if (s == SEQ - 1) g_last2[b * HD + hid] = h;
        }
        __syncthreads();                             // local sH + pushes issued
        if (s < SEQ - 1)                             // release; matched by wait(s+1)
            asm volatile("barrier.cluster.arrive.aligned;" ::: "memory");
        gxv = gxn;
    }
}

// ---------------- FC: out[b][n] = last[b] . fc_w[n] + fc_b[n] (f32x2) ------
__global__ void __launch_bounds__(128) k_fc(const float* __restrict__ fw,
                                            const float* __restrict__ fb,
                                            float* __restrict__ out) {
    __shared__ float As[128][64];   // [k][b]
    __shared__ float Bs[16][128];   // [k][n]
    int n0 = blockIdx.x * 128;
    int tid = threadIdx.x;
    int tc = tid & 15, tr = tid >> 4;
    for (int i = tid; i < 64 * 128; i += 128) {
        int bb = i >> 7, kk = i & 127;
        As[kk][bb] = g_last2[bb * HD + kk];
    }
    unsigned long long acc[8][4] = {};
    for (int k0 = 0; k0 < 128; k0 += 16) {
        float4 f0 = *(const float4*)(fw + (size_t)(n0 + tid) * 128 + k0);
        float4 f1 = *(const float4*)(fw + (size_t)(n0 + tid) * 128 + k0 + 4);
        float4 f2 = *(const float4*)(fw + (size_t)(n0 + tid) * 128 + k0 + 8);
        float4 f3 = *(const float4*)(fw + (size_t)(n0 + tid) * 128 + k0 + 12);
        __syncthreads();
        Bs[0][tid] = f0.x;  Bs[1][tid] = f0.y;  Bs[2][tid] = f0.z;  Bs[3][tid] = f0.w;
        Bs[4][tid] = f1.x;  Bs[5][tid] = f1.y;  Bs[6][tid] = f1.z;  Bs[7][tid] = f1.w;
        Bs[8][tid] = f2.x;  Bs[9][tid] = f2.y;  Bs[10][tid] = f2.z; Bs[11][tid] = f2.w;
        Bs[12][tid] = f3.x; Bs[13][tid] = f3.y; Bs[14][tid] = f3.z; Bs[15][tid] = f3.w;
        __syncthreads();
#pragma unroll
        for (int k = 0; k < 16; k++) {
            float av[8];
            *(float4*)&av[0] = *(const float4*)&As[k0 + k][tr * 8];
            *(float4*)&av[4] = *(const float4*)&As[k0 + k][tr * 8 + 4];
            ulonglong2 q0 = *(const ulonglong2*)&Bs[k][tc * 8];
            ulonglong2 q1 = *(const ulonglong2*)&Bs[k][tc * 8 + 4];
            unsigned long long bv[4] = {q0.x, q0.y, q1.x, q1.y};
#pragma unroll
            for (int i = 0; i < 8; i++) {
                U2 ap; ap.f.x = av[i]; ap.f.y = av[i];
#pragma unroll
                for (int jj = 0; jj < 4; jj++) FMA2(acc[i][jj], ap.u, bv[jj]);
            }
        }
    }
#pragma unroll
    for (int i = 0; i < 8; i++) {
        int m = tr * 8 + i;                       // batch index 0..63
        float o[8];
#pragma unroll
        for (int jj = 0; jj < 4; jj++) {
            U2 v; v.u = acc[i][jj];
            o[2 * jj] = v.f.x + fb[n0 + tc * 8 + 2 * jj];
            o[2 * jj + 1] = v.f.y + fb[n0 + tc * 8 + 2 * jj + 1];
        }
        *(float4*)(out + (size_t)m * FCN + n0 + tc * 8) = *(float4*)&o[0];
        *(float4*)(out + (size_t)m * FCN + n0 + tc * 8 + 4) = *(float4*)&o[4];
    }
}

extern "C" void kernel_launch(void* const* d_in, const int* in_sizes, int n_in,
                              void* d_out, int out_size) {
    const float* x   = (const float*)d_in[0];
    const int*   ei  = (const int*)d_in[1];     // int64 in reference -> int32 on device
    const float* ew  = (const float*)d_in[2];
    // d_in[3] = batch (int32, unused by reference math)
    const float* Wg  = (const float*)d_in[4];
    const float* bg  = (const float*)d_in[5];
    const float* wih = (const float*)d_in[6];
    const float* whh = (const float*)d_in[7];
    const float* bih = (const float*)d_in[8];
    const float* bhh = (const float*)d_in[9];
    const float* fw  = (const float*)d_in[10];
    const float* fb  = (const float*)d_in[11];
    float* out       = (float*)d_out;

    k_deg_init<<<TN / 256, 256>>>();
    k_deg_acc<<<NE / 256, 256>>>(ei, ew);
    k_dinv<<<TN / 256, 256>>>();
    k_scan<<<1, 1024>>>();
    k_fill<<<NE / 256, 256>>>(ei);
    k_xw<<<TN / 128, 256>>>(x, Wg, bg);
    k_gather<<<TN / 8, 256>>>(ei, ew);

    dim3 gg(G4 / 128, TN / 128);
    // layer 0
    k_gates<<<gg, 256>>>(wih, bih, bhh, 0);
    k_rec<<<NB * 2, 256>>>(whh, 0);
    // layer 1
    k_gates<<<gg, 256>>>(wih + 512 * 128, bih + 512, bhh + 512, 1);
    k_rec<<<NB * 2, 256>>>(whh + 512 * 128, 1);

    k_fc<<<FCN / 128, 128>>>(fw, fb, out);
}

// round 17
// speedup vs baseline: 1.4188x; 1.4188x over previous
#include <cuda_runtime.h>
#include <cstdint>
#include <cstddef>

#define TN 32768
#define NB 64
#define SEQ 512
#define HD 128
#define G4 512
#define NE 1048576
#define FCN 262144

// ---------------- scratch (device globals; allocation-free) ----------------
__device__ float g_deg[TN];          // deg -> dinv (in place)
__device__ float g_xw[TN * HD];      // x @ W_gcn (pre-norm)
__device__ float g_h[TN * HD];       // GCN output / LSTM-1 input
__device__ float g_gates[TN * G4];   // 64 MB x-part gate buffer (reused per layer)
__device__ float g_seq1[TN * HD];    // LSTM layer-1 output sequence
__device__ float g_last2[NB * HD];   // LSTM layer-2 LAST hidden (FC input)
// dst-CSR for the edge scatter (int only; no float atomics anywhere)
__device__ int g_cnt[TN];
__device__ int g_cur[TN];
__device__ int g_off[TN + 1];
__device__ int g_eid[NE];

#define FMA2(a, b, c) asm("fma.rn.f32x2 %0,%1,%2,%0;" : "+l"(a) : "l"(b), "l"(c))
union U2 { unsigned long long u; float2 f; };

__device__ __forceinline__ float fsig(float x) {        // sigmoid, MUFU-based
    return __fdividef(1.0f, 1.0f + __expf(-x));
}
__device__ __forceinline__ float ftanh(float x) {       // tanh via exp, ~1e-6 err
    return 1.0f - __fdividef(2.0f, __expf(2.0f * x) + 1.0f);
}
__device__ __forceinline__ uint32_t smem_u32(const void* p) {
    uint32_t a;
    asm("{ .reg .u64 t; cvta.to.shared.u64 t, %1; cvt.u32.u64 %0, t; }" : "=r"(a) : "l"(p));
    return a;
}

// ---------------- degree / norm / CSR count ----------------
__global__ void k_deg_init() {
    int i = blockIdx.x * 256 + threadIdx.x;
    g_deg[i] = 1.0f;                                 // self-loop weight
    g_cnt[i] = 0;
    g_cur[i] = 0;
}
// edge_index is int32 on the device (harness downcasts int64 inputs).
__global__ void k_deg_acc(const int* __restrict__ ei, const float* __restrict__ ew) {
    int e = blockIdx.x * 256 + threadIdx.x;
    int d = ei[NE + e];
    atomicAdd(&g_deg[d], ew[e]);
    atomicAdd(&g_cnt[d], 1);
}
__global__ void k_dinv() {
    int i = blockIdx.x * 256 + threadIdx.x;
    g_deg[i] = rsqrtf(g_deg[i]);                     // deg >= 1 always
}

// ---------------- exclusive scan of g_cnt -> g_off (1 block, 1024 thr) -----
__global__ void __launch_bounds__(1024) k_scan() {
    __shared__ int ssum[1024];
    int t = threadIdx.x;
    int base = t * 32;
    int loc[32];
    int s = 0;
    const int4* cp = (const int4*)(g_cnt + base);
#pragma unroll
    for (int i = 0; i < 8; i++) {
        int4 q = cp[i];
        loc[4 * i + 0] = s; s += q.x;
        loc[4 * i + 1] = s; s += q.y;
        loc[4 * i + 2] = s; s += q.z;
        loc[4 * i + 3] = s; s += q.w;
    }
    ssum[t] = s;
    __syncthreads();
    for (int d = 1; d < 1024; d <<= 1) {
        int v = (t >= d) ? ssum[t - d] : 0;
        __syncthreads();
        ssum[t] += v;
        __syncthreads();
    }
    int excl = (t == 0) ? 0 : ssum[t - 1];
    int4* op = (int4*)(g_off + base);
#pragma unroll
    for (int i = 0; i < 8; i++) {
        int4 q;
        q.x = excl + loc[4 * i + 0];
        q.y = excl + loc[4 * i + 1];
        q.z = excl + loc[4 * i + 2];
        q.w = excl + loc[4 * i + 3];
        op[i] = q;
    }
    if (t == 1023) g_off[TN] = ssum[1023];
}

__global__ void k_fill(const int* __restrict__ ei) {
    int e = blockIdx.x * 256 + threadIdx.x;
    int d = ei[NE + e];
    int pos = g_off[d] + atomicAdd(&g_cur[d], 1);
    g_eid[pos] = e;
}

// ---------------- xw = x @ W_gcn ; g_h = b_gcn + dinv^2 * xw ----------------
__global__ void __launch_bounds__(256) k_xw(const float* __restrict__ X,
                                            const float* __restrict__ W,
                                            const float* __restrict__ bg) {
    __shared__ float As[16][128];
    __shared__ float Bs[16][128];
    int m0 = blockIdx.x * 128;
    int tid = threadIdx.x;
    int tc = tid & 15, tr = tid >> 4;
    int lr = tid >> 1, lc = (tid & 1) * 8;           // A loader
    int bk = tid >> 4, bn = (tid & 15) * 8;          // B loader
    float acc[8][8] = {};
    for (int k0 = 0; k0 < 128; k0 += 16) {
        float4 a0 = *(const float4*)(X + (size_t)(m0 + lr) * 128 + k0 + lc);
        float4 a1 = *(const float4*)(X + (size_t)(m0 + lr) * 128 + k0 + lc + 4);
        float4 b0 = *(const float4*)(W + (size_t)(k0 + bk) * 128 + bn);
        float4 b1 = *(const float4*)(W + (size_t)(k0 + bk) * 128 + bn + 4);
        __syncthreads();
        As[lc + 0][lr] = a0.x; As[lc + 1][lr] = a0.y; As[lc + 2][lr] = a0.z; As[lc + 3][lr] = a0.w;
        As[lc + 4][lr] = a1.x; As[lc + 5][lr] = a1.y; As[lc + 6][lr] = a1.z; As[lc + 7][lr] = a1.w;
        *(float4*)&Bs[bk][bn] = b0;
        *(float4*)&Bs[bk][bn + 4] = b1;
        __syncthreads();
#pragma unroll
        for (int k = 0; k < 16; k++) {
            float av[8], bv[8];
            *(float4*)&av[0] = *(const float4*)&As[k][tr * 8];
            *(float4*)&av[4] = *(const float4*)&As[k][tr * 8 + 4];
            *(float4*)&bv[0] = *(const float4*)&Bs[k][tc * 8];
            *(float4*)&bv[4] = *(const float4*)&Bs[k][tc * 8 + 4];
#pragma unroll
            for (int i = 0; i < 8; i++)
#pragma unroll
                for (int jj = 0; jj < 8; jj++)
                    acc[i][jj] = fmaf(av[i], bv[jj], acc[i][jj]);
        }
    }
#pragma unroll
    for (int i = 0; i < 8; i++) {
        int m = m0 + tr * 8 + i;
        float di = g_deg[m];
        float di2 = di * di;
#pragma unroll
        for (int jj = 0; jj < 8; jj++) {
            int n = tc * 8 + jj;
            float v = acc[i][jj];
            g_xw[(size_t)m * 128 + n] = v;
            g_h[(size_t)m * 128 + n] = bg[n] + v * di2;
        }
    }
}

// ---------------- gather: g_h[d] += sum_e norm_e * g_xw[src_e] -------------
__global__ void __launch_bounds__(256) k_gather(const int* __restrict__ ei,
                                                const float* __restrict__ ew) {
    int d = blockIdx.x * 8 + (threadIdx.x >> 5);
    int lane = threadIdx.x & 31;
    int beg = g_off[d], end = g_off[d + 1];
    float dd = g_deg[d];
    float4 acc = {0.f, 0.f, 0.f, 0.f};
    int p = beg;
    for (; p + 2 <= end; p += 2) {
        int e0 = g_eid[p], e1 = g_eid[p + 1];
        int s0 = ei[e0], s1 = ei[e1];
        float n0 = g_deg[s0] * ew[e0] * dd;
        float n1 = g_deg[s1] * ew[e1] * dd;
        float4 v0 = ((const float4*)(g_xw + (size_t)s0 * HD))[lane];
        float4 v1 = ((const float4*)(g_xw + (size_t)s1 * HD))[lane];
        acc.x = fmaf(n0, v0.x, fmaf(n1, v1.x, acc.x));
        acc.y = fmaf(n0, v0.y, fmaf(n1, v1.y, acc.y));
        acc.z = fmaf(n0, v0.z, fmaf(n1, v1.z, acc.z));
        acc.w = fmaf(n0, v0.w, fmaf(n1, v1.w, acc.w));
    }
    if (p < end) {
        int e0 = g_eid[p];
        int s0 = ei[e0];
        float n0 = g_deg[s0] * ew[e0] * dd;
        float4 v0 = ((const float4*)(g_xw + (size_t)s0 * HD))[lane];
        acc.x = fmaf(n0, v0.x, acc.x); acc.y = fmaf(n0, v0.y, acc.y);
        acc.z = fmaf(n0, v0.z, acc.z); acc.w = fmaf(n0, v0.w, acc.w);
    }
    float4* dst = (float4*)(g_h + (size_t)d * HD) + lane;
    float4 cur = *dst;                               // bias + self-loop term
    cur.x += acc.x; cur.y += acc.y; cur.z += acc.z; cur.w += acc.w;
    *dst = cur;
}

// ---------------- gate GEMM: g_gates = A @ wih^T + bih + bhh (f32x2) -------
__global__ void __launch_bounds__(256) k_gates(const float* __restrict__ Bw,
                                               const float* __restrict__ c1,
                                               const float* __restrict__ c2, int src) {
    const float* A = src ? g_seq1 : g_h;
    __shared__ float As[16][128];
    __shared__ float Bs[16][128];
    int m0 = blockIdx.y * 128, n0 = blockIdx.x * 128;
    int tid = threadIdx.x;
    int tc = tid & 15, tr = tid >> 4;
    int lr = tid >> 1, lc = (tid & 1) * 8;
    unsigned long long acc[8][4] = {};
    for (int k0 = 0; k0 < 128; k0 += 16) {
        float4 a0 = *(const float4*)(A + (size_t)(m0 + lr) * 128 + k0 + lc);
        float4 a1 = *(const float4*)(A + (size_t)(m0 + lr) * 128 + k0 + lc + 4);
        float4 p0 = *(const float4*)(Bw + (size_t)(n0 + lr) * 128 + k0 + lc);
        float4 p1 = *(const float4*)(Bw + (size_t)(n0 + lr) * 128 + k0 + lc + 4);
        __syncthreads();
        As[lc + 0][lr] = a0.x; As[lc + 1][lr] = a0.y; As[lc + 2][lr] = a0.z; As[lc + 3][lr] = a0.w;
        As[lc + 4][lr] = a1.x; As[lc + 5][lr] = a1.y; As[lc + 6][lr] = a1.z; As[lc + 7][lr] = a1.w;
        Bs[lc + 0][lr] = p0.x; Bs[lc + 1][lr] = p0.y; Bs[lc + 2][lr] = p0.z; Bs[lc + 3][lr] = p0.w;
        Bs[lc + 4][lr] = p1.x; Bs[lc + 5][lr] = p1.y; Bs[lc + 6][lr] = p1.z; Bs[lc + 7][lr] = p1.w;
        __syncthreads();
#pragma unroll
        for (int k = 0; k < 16; k++) {
            float av[8];
            *(float4*)&av[0] = *(const float4*)&As[k][tr * 8];
            *(float4*)&av[4] = *(const float4*)&As[k][tr * 8 + 4];
            ulonglong2 q0 = *(const ulonglong2*)&Bs[k][tc * 8];
            ulonglong2 q1 = *(const ulonglong2*)&Bs[k][tc * 8 + 4];
            unsigned long long bv[4] = {q0.x, q0.y, q1.x, q1.y};
#pragma unroll
            for (int i = 0; i < 8; i++) {
                U2 ap; ap.f.x = av[i]; ap.f.y = av[i];
#pragma unroll
                for (int jj = 0; jj < 4; jj++) FMA2(acc[i][jj], ap.u, bv[jj]);
            }
        }
    }
    float bias[8];
#pragma unroll
    for (int jj = 0; jj < 8; jj++) {
        int n = n0 + tc * 8 + jj;
        bias[jj] = c1[n] + c2[n];
    }
#pragma unroll
    for (int i = 0; i < 8; i++) {
        int m = m0 + tr * 8 + i;
        float o[8];
#pragma unroll
        for (int jj = 0; jj < 4; jj++) {
            U2 v; v.u = acc[i][jj];
            o[2 * jj] = v.f.x + bias[2 * jj];
            o[2 * jj + 1] = v.f.y + bias[2 * jj + 1];
        }
        *(float4*)(g_gates + (size_t)m * 512 + n0 + tc * 8) = *(float4*)&o[0];
        *(float4*)(g_gates + (size_t)m * 512 + n0 + tc * 8 + 4) = *(float4*)&o[4];
    }
}

// ---------------- LSTM recurrence: 2-CTA cluster per batch -----------------
// R14 sync (ADJACENT arrive+wait each step — fused fast path) + gate remap:
// CTA r owns cols {t*128 + r*64 + hl}, so activation for h-idx [r*64,r*64+64)
// is CTA-local; only 64 h floats cross the cluster per step (vs 1KB of gates
// in R14), and activation is not computed redundantly.
// sH parity double-buffered: act(s)/peer-push(s) write buf s&1, read only by
// dot(s+1) which is after barrier(s); dot(s) reads buf (s+1)&1 written at
// s-1 before barrier(s-1). All conflicts ordered by the barrier chain.
__global__ void __launch_bounds__(256, 1) __cluster_dims__(2, 1, 1)
k_rec(const float* __restrict__ whh, int layer) {
    __shared__ float sH[2][HD];
    __shared__ float sGl[256];
    int j = threadIdx.x;
    unsigned rank;
    asm("mov.u32 %0, %%cluster_ctarank;" : "=r"(rank));
    int b = blockIdx.x >> 1;                         // batch id
    int t = j >> 6;                                  // gate type 0..3 (i,f,g,o)
    int hl = j & 63;                                 // local h index
    int hid = rank * 64 + hl;                        // global h index
    int gcol = t * 128 + hid;                        // owned gate column
    const unsigned long long* wrow = (const unsigned long long*)(whh + (size_t)gcol * HD);
    unsigned long long wr[64];
#pragma unroll
    for (int p = 0; p < 64; p++) wr[p] = wrow[p];    // full whh row in registers
    uint32_t sh_local = smem_u32(&sH[0][0]);
    uint32_t sh_peer;
    asm("mapa.shared::cluster.u32 %0, %1, %2;" : "=r"(sh_peer) : "r"(sh_local), "r"(rank ^ 1u));
    if (j < HD) sH[1][j] = 0.0f;                     // step-0 dot reads buf 1
    float c = 0.0f;
    __syncthreads();
    asm volatile("barrier.cluster.arrive.aligned;" ::: "memory");
    asm volatile("barrier.cluster.wait.aligned;" ::: "memory");

    const float* gxb = g_gates + (size_t)b * SEQ * G4 + gcol;
    float* hob = g_seq1 + (size_t)b * SEQ * HD;
    float gxv = gxb[0];
    for (int s = 0; s < SEQ; s++) {
        float gxn = (s < SEQ - 1) ? gxb[(size_t)(s + 1) * G4] : 0.0f;
        const ulonglong2* h2 = (const ulonglong2*)sH[(s + 1) & 1];
        unsigned long long a0 = 0ULL, a1 = 0ULL;
#pragma unroll
        for (int q = 0; q < 32; q++) {               // full 128-wide dot (regs)
            ulonglong2 hh = h2[q];
            FMA2(a0, wr[2 * q], hh.x);
            FMA2(a1, wr[2 * q + 1], hh.y);
        }
        U2 u0, u1; u0.u = a0; u1.u = a1;
        sGl[j] = gxv + (u0.f.x + u0.f.y) + (u1.f.x + u1.f.y);
        __syncthreads();
        if (j < 64) {                                // all 4 gates CTA-local
            float gi = sGl[j], gf = sGl[64 + j], gg = sGl[128 + j], go = sGl[192 + j];
            c = fsig(gf) * c + fsig(gi) * ftanh(gg);
            float h = fsig(go) * ftanh(c);
            int wb = s & 1;
            sH[wb][hid] = h;
            if (s < SEQ - 1) {                       // push our 64-float half
                uint32_t off = (uint32_t)(wb * HD + hid) * 4u;
                asm volatile("st.shared::cluster.f32 [%0], %1;"
                             :: "r"(sh_peer + off), "f"(h) : "memory");
            }
            if (layer == 0) hob[(size_t)s * HD + hid] = h;
            else if (s == SEQ - 1) g_last2[b * HD + hid] = h;
        }
        __syncthreads();                             // local sH + pushes issued
        if (s < SEQ - 1) {                           // ADJACENT pair: fused path
            asm volatile("barrier.cluster.arrive.aligned;" ::: "memory");
            asm volatile("barrier.cluster.wait.aligned;" ::: "memory");
        }
        gxv = gxn;
    }
}

// ---------------- FC: out[b][n] = last[b] . fc_w[n] + fc_b[n] (f32x2) ------
__global__ void __launch_bounds__(128) k_fc(const float* __restrict__ fw,
                                            const float* __restrict__ fb,
                                            float* __restrict__ out) {
    __shared__ float As[128][64];   // [k][b]
    __shared__ float Bs[16][128];   // [k][n]
    int n0 = blockIdx.x * 128;
    int tid = threadIdx.x;
    int tc = tid & 15, tr = tid >> 4;
    for (int i = tid; i < 64 * 128; i += 128) {
        int bb = i >> 7, kk = i & 127;
        As[kk][bb] = g_last2[bb * HD + kk];
    }
    unsigned long long acc[8][4] = {};
    for (int k0 = 0; k0 < 128; k0 += 16) {
        float4 f0 = *(const float4*)(fw + (size_t)(n0 + tid) * 128 + k0);
        float4 f1 = *(const float4*)(fw + (size_t)(n0 + tid) * 128 + k0 + 4);
        float4 f2 = *(const float4*)(fw + (size_t)(n0 + tid) * 128 + k0 + 8);
        float4 f3 = *(const float4*)(fw + (size_t)(n0 + tid) * 128 + k0 + 12);
        __syncthreads();
        Bs[0][tid] = f0.x;  Bs[1][tid] = f0.y;  Bs[2][tid] = f0.z;  Bs[3][tid] = f0.w;
        Bs[4][tid] = f1.x;  Bs[5][tid] = f1.y;  Bs[6][tid] = f1.z;  Bs[7][tid] = f1.w;
        Bs[8][tid] = f2.x;  Bs[9][tid] = f2.y;  Bs[10][tid] = f2.z; Bs[11][tid] = f2.w;
        Bs[12][tid] = f3.x; Bs[13][tid] = f3.y; Bs[14][tid] = f3.z; Bs[15][tid] = f3.w;
        __syncthreads();
#pragma unroll
        for (int k = 0; k < 16; k++) {
            float av[8];
            *(float4*)&av[0] = *(const float4*)&As[k0 + k][tr * 8];
            *(float4*)&av[4] = *(const float4*)&As[k0 + k][tr * 8 + 4];
            ulonglong2 q0 = *(const ulonglong2*)&Bs[k][tc * 8];
            ulonglong2 q1 = *(const ulonglong2*)&Bs[k][tc * 8 + 4];
            unsigned long long bv[4] = {q0.x, q0.y, q1.x, q1.y};
#pragma unroll
            for (int i = 0; i < 8; i++) {
                U2 ap; ap.f.x = av[i]; ap.f.y = av[i];
#pragma unroll
                for (int jj = 0; jj < 4; jj++) FMA2(acc[i][jj], ap.u, bv[jj]);
            }
        }
    }
#pragma unroll
    for (int i = 0; i < 8; i++) {
        int m = tr * 8 + i;                       // batch index 0..63
        float o[8];
#pragma unroll
        for (int jj = 0; jj < 4; jj++) {
            U2 v; v.u = acc[i][jj];
            o[2 * jj] = v.f.x + fb[n0 + tc * 8 + 2 * jj];
            o[2 * jj + 1] = v.f.y + fb[n0 + tc * 8 + 2 * jj + 1];
        }
        *(float4*)(out + (size_t)m * FCN + n0 + tc * 8) = *(float4*)&o[0];
        *(float4*)(out + (size_t)m * FCN + n0 + tc * 8 + 4) = *(float4*)&o[4];
    }
}

extern "C" void kernel_launch(void* const* d_in, const int* in_sizes, int n_in,
                              void* d_out, int out_size) {
    const float* x   = (const float*)d_in[0];
    const int*   ei  = (const int*)d_in[1];     // int64 in reference -> int32 on device
    const float* ew  = (const float*)d_in[2];
    // d_in[3] = batch (int32, unused by reference math)
    const float* Wg  = (const float*)d_in[4];
    const float* bg  = (const float*)d_in[5];
    const float* wih = (const float*)d_in[6];
    const float* whh = (const float*)d_in[7];
    const float* bih = (const float*)d_in[8];
    const float* bhh = (const float*)d_in[9];
    const float* fw  = (const float*)d_in[10];
    const float* fb  = (const float*)d_in[11];
    float* out       = (float*)d_out;

    k_deg_init<<<TN / 256, 256>>>();
    k_deg_acc<<<NE / 256, 256>>>(ei, ew);
    k_dinv<<<TN / 256, 256>>>();
    k_scan<<<1, 1024>>>();
    k_fill<<<NE / 256, 256>>>(ei);
    k_xw<<<TN / 128, 256>>>(x, Wg, bg);
    k_gather<<<TN / 8, 256>>>(ei, ew);

    dim3 gg(G4 / 128, TN / 128);
    // layer 0
    k_gates<<<gg, 256>>>(wih, bih, bhh, 0);
    k_rec<<<NB * 2, 256>>>(whh, 0);
    // layer 1
    k_gates<<<gg, 256>>>(wih + 512 * 128, bih + 512, bhh + 512, 1);
    k_rec<<<NB * 2, 256>>>(whh + 512 * 128, 1);

    k_fc<<<FCN / 128, 128>>>(fw, fb, out);
}